// round 3
// baseline (speedup 1.0000x reference)
#include <cuda_runtime.h>
#include <cstdint>

#define DB 64
#define DS 2048
#define DI 64
#define DH 128

typedef unsigned long long u64;

// ---------------- scratch (__device__ globals) -------------------------------
__device__ float g_wx0 [DB * DS * DH];   // x @ w0      (producer gemm warps)
__device__ float g_out0[DB * DS * DH];   // layer-0 outputs (producer scan)
__device__ float g_wx1 [DB * DS * DH];   // out0 @ w1   (consumer gemm warps)
__device__ int   g_prog[DB * 32];        // [b*32+0]=p0  [+8]=pW0  [+16]=pW1

// ---------------- packed f32x2 helpers ---------------------------------------
__device__ __forceinline__ u64 ffma2(u64 a, u64 b, u64 c) {
    u64 d; asm("fma.rn.f32x2 %0, %1, %2, %3;" : "=l"(d) : "l"(a), "l"(b), "l"(c)); return d;
}
__device__ __forceinline__ u64 fadd2(u64 a, u64 b) {
    u64 d; asm("add.rn.f32x2 %0, %1, %2;" : "=l"(d) : "l"(a), "l"(b)); return d;
}
__device__ __forceinline__ u64 dup2(float x) {
    u64 d; asm("mov.b64 %0, {%1, %2};" : "=l"(d) : "f"(x), "f"(x)); return d;
}
__device__ __forceinline__ u64 pk2(float lo, float hi) {
    u64 d; asm("mov.b64 %0, {%1, %2};" : "=l"(d) : "f"(lo), "f"(hi)); return d;
}
__device__ __forceinline__ float2 unp2(u64 v) {
    float lo, hi; asm("mov.b64 {%0, %1}, %2;" : "=f"(lo), "=f"(hi) : "l"(v));
    return make_float2(lo, hi);
}

// ---------------- activations -------------------------------------------------
__device__ __forceinline__ float sigm(float x) {
    float e = __expf(fminf(-x, 30.f));
    return __fdividef(1.f, 1.f + e);
}
__device__ __forceinline__ float tanh_f(float x) {
    float xc = fminf(fmaxf(x, -15.f), 15.f);
    float e  = __expf(2.f * xc);
    return __fdividef(e - 1.f, e + 1.f);
}

// ---------------- flags --------------------------------------------------------
__device__ __forceinline__ int ld_acq(const int* p) {
    int v; asm volatile("ld.acquire.gpu.b32 %0, [%1];" : "=r"(v) : "l"(p)); return v;
}
__device__ __forceinline__ void st_rel(int* p, int v) {
    asm volatile("st.release.gpu.b32 [%0], %1;" :: "l"(p), "r"(v));
}
__device__ __forceinline__ void spin_ge(const int* p, int target) {
    while (ld_acq(p) < target) __nanosleep(40);
}

#define NB1() asm volatile("bar.sync 1, 256;" ::: "memory")
#define NB2() asm volatile("bar.sync 2, 256;" ::: "memory")

__global__ void reset_kernel() {
    int i = blockIdx.x * blockDim.x + threadIdx.x;
    if (i < DB * 32) g_prog[i] = 0;
}

// ============================================================================
// GEMM role (warps 8-15, gtid 0..255): wx[t, 0:128] = SRC[t, 0:KW] @ Wpack
// Tiles of 8 steps. warp = tile row, lane = column-pair (owns pairs l, l+32).
// ============================================================================
template<int KW>
__device__ __forceinline__ void gemm_role(
    const float* __restrict__ src, const float4* __restrict__ wpack,
    float* __restrict__ stage, float* __restrict__ wxdst,
    const int* waitflag, int* postflag, int gtid)
{
    const int r = gtid >> 5;        // tile row 0..7
    const int l = gtid & 31;        // column-pair lane

    #pragma unroll 1
    for (int tile = 0; tile < DS / 8; tile++) {
        const int t0 = tile * 8;
        if (waitflag) {
            if (gtid == 0) { spin_ge(waitflag, t0 + 8); __threadfence(); }
        }
        NB2();                      // stage reuse safe + after-spin ordering
        // stage SRC rows t0..t0+7 (8*KW floats)
        for (int e = gtid; e < 8 * KW / 4; e += 256)
            reinterpret_cast<float4*>(stage)[e] =
                reinterpret_cast<const float4*>(src + (size_t)t0 * KW)[e];
        NB2();

        const float* orow = stage + r * KW;
        u64 a0 = 0, b0 = 0, a1 = 0, b1 = 0;
        #pragma unroll 8
        for (int k2 = 0; k2 < KW / 2; k2++) {
            float2 o2 = *reinterpret_cast<const float2*>(orow + 2 * k2);
            u64 d0 = dup2(o2.x), d1 = dup2(o2.y);
            float4 wa = wpack[k2 * 64 + l];
            float4 wb = wpack[k2 * 64 + l + 32];
            a0 = ffma2(d0, pk2(wa.x, wa.y), a0);
            b0 = ffma2(d1, pk2(wa.z, wa.w), b0);
            a1 = ffma2(d0, pk2(wb.x, wb.y), a1);
            b1 = ffma2(d1, pk2(wb.z, wb.w), b1);
        }
        *reinterpret_cast<u64*>(wxdst + (size_t)(t0 + r) * DH + 2 * l)      = fadd2(a0, b0);
        *reinterpret_cast<u64*>(wxdst + (size_t)(t0 + r) * DH + 64 + 2 * l) = fadd2(a1, b1);
        __threadfence();
        NB2();
        if (gtid == 0) st_rel(postflag, t0 + 8);
    }
}

// ============================================================================
// Scan role (warps 0-7, tid 0..255): thread = (col j = tid>>1, khalf = tid&1).
// pre[j] = wx[s][j] + sum_k h[k]*u[k][j]; k-halves combined via shfl.xor(1).
// One named barrier per step.
// ============================================================================
__device__ __forceinline__ void scan_role(
    float* __restrict__ hbuf,
    const float* __restrict__ umat, const float* __restrict__ wxr,
    const float* __restrict__ bg, const float* __restrict__ bu,
    const float* __restrict__ zeta, const float* __restrict__ nu,
    const float* __restrict__ lambd, const float* __restrict__ gamma,
    float* __restrict__ outp, float* __restrict__ hT,
    const int* pwx, int* p0, int layer, int tid)
{
    const int j  = tid >> 1;
    const int kh = tid & 1;

    // weights: k-pair packed {u[k][j], u[k+1][j]} for k in [kh*64, kh*64+64)
    u64 uk[32];
    #pragma unroll
    for (int i = 0; i < 32; i++) {
        int k = kh * 64 + 2 * i;
        uk[i] = pk2(umat[(size_t)k * DH + j], umat[(size_t)(k + 1) * DH + j]);
    }
    const float bgj  = bg[j], buj = bu[j];
    const float sz   = sigm(zeta[0]);
    const float sn   = sigm(nu[0]);
    const float gc   = fminf(fmaxf(gamma[0], 0.f), 1.f);
    const float cadd = (1.f - gc) * lambd[0];

    hbuf[tid] = 0.f;                 // zero both h buffers (256 floats)

    if (tid == 0) { spin_ge(pwx, 16); __threadfence(); }
    NB1();

    float wxA = wxr[j], wxB = wxr[DH + j], hold = 0.f;

    #pragma unroll 1
    for (int s = 0; s < DS; s++) {
        if ((s & 7) == 0 && s) {
            if (tid == 0) {
                int tgt = s + 10; if (tgt > DS) tgt = DS;
                spin_ge(pwx, tgt); __threadfence();
            }
            NB1();
        }
        const float4* hp = reinterpret_cast<const float4*>(hbuf + (s & 1) * DH + kh * 64);
        u64 a0 = 0, a1 = 0, a2 = 0, a3 = 0;
        #pragma unroll
        for (int i = 0; i < 16; i += 2) {
            float4 h0 = hp[i], h1 = hp[i + 1];
            a0 = ffma2(pk2(h0.x, h0.y), uk[2 * i],     a0);
            a1 = ffma2(pk2(h0.z, h0.w), uk[2 * i + 1], a1);
            a2 = ffma2(pk2(h1.x, h1.y), uk[2 * i + 2], a2);
            a3 = ffma2(pk2(h1.z, h1.w), uk[2 * i + 3], a3);
        }
        u64 acc = fadd2(fadd2(a0, a1), fadd2(a2, a3));
        u64 oth = __shfl_xor_sync(0xFFFFFFFFu, acc, 1);
        acc = fadd2(acc, oth);
        float2 ap = unp2(acc);
        float pre = (ap.x + ap.y) + wxA;

        float zg = sigm(pre + bgj);
        float hh = tanh_f(pre + buj);
        float hn = zg * hold + (sz * (1.f - zg) + sn) * hh;
        float hc = __fmaf_rn(gc, hn, cadd);
        hold = hc;
        if (kh == 0) {
            hbuf[((s & 1) ^ 1) * DH + j] = hc;
            outp[(size_t)s * DH + j] = hc;
        }
        wxA = wxB;
        wxB = (s + 2 < DS) ? wxr[(size_t)(s + 2) * DH + j] : 0.f;

        if (layer == 0 && (s & 7) == 7) __threadfence();
        NB1();
        if (layer == 0 && (s & 7) == 7 && tid == 0) st_rel(p0, s + 1);
    }
    if (kh == 0) hT[j] = hold;
}

// ============================================================================
__global__ void __launch_bounds__(512, 1) fused_kernel(
    const float* __restrict__ x,
    const float* __restrict__ w0, const float* __restrict__ u0,
    const float* __restrict__ bg0, const float* __restrict__ bu0,
    const float* __restrict__ zeta0, const float* __restrict__ nu0,
    const float* __restrict__ lambd0, const float* __restrict__ gamma0,
    const float* __restrict__ w1, const float* __restrict__ u1,
    const float* __restrict__ bg1, const float* __restrict__ bu1,
    const float* __restrict__ zeta1, const float* __restrict__ nu1,
    const float* __restrict__ lambd1, const float* __restrict__ gamma1,
    float* __restrict__ out1, float* __restrict__ hT0, float* __restrict__ hT1)
{
    extern __shared__ __align__(16) unsigned char smraw[];
    float4* wpack = reinterpret_cast<float4*>(smraw);            // <=64KB
    float*  stage = reinterpret_cast<float*>(smraw + 65536);     // 4KB
    float*  hbuf  = reinterpret_cast<float*>(smraw + 65536 + 4096); // 1KB

    const int layer = blockIdx.x >> 6;
    const int b     = blockIdx.x & 63;
    const int tid   = threadIdx.x;

    const float* wmat = layer ? w1 : w0;
    const int    KW   = layer ? DH : DI;
    float* out0b = g_out0 + (size_t)b * DS * DH;
    float* wxbuf = (layer ? g_wx1 : g_wx0) + (size_t)b * DS * DH;
    int*   prog  = g_prog + b * 32;
    int*   p0    = prog;
    int*   pwx   = prog + 8 + layer * 8;        // pW0 / pW1

    // cooperative load of packed projection weights: wpack[k2][j2] =
    // {w[2k2][2j2], w[2k2][2j2+1], w[2k2+1][2j2], w[2k2+1][2j2+1]}
    for (int e = tid; e < (KW / 2) * 64; e += 512) {
        int k2 = e >> 6, j2 = e & 63;
        const float* r0 = wmat + (size_t)(2 * k2) * DH + 2 * j2;
        float4 v; v.x = r0[0]; v.y = r0[1]; v.z = r0[DH]; v.w = r0[DH + 1];
        wpack[(size_t)k2 * 64 + j2] = v;
    }
    __syncthreads();

    if (tid < 256) {
        scan_role(hbuf,
                  layer ? u1 : u0, wxbuf,
                  layer ? bg1 : bg0, layer ? bu1 : bu0,
                  layer ? zeta1 : zeta0, layer ? nu1 : nu0,
                  layer ? lambd1 : lambd0, layer ? gamma1 : gamma0,
                  layer ? (out1 + (size_t)b * DS * DH) : out0b,
                  (layer ? hT1 : hT0) + (size_t)b * DH,
                  pwx, p0, layer, tid);
    } else {
        if (layer == 0)
            gemm_role<DI>(x + (size_t)b * DS * DI, wpack, stage, wxbuf,
                          nullptr, pwx, tid - 256);
        else
            gemm_role<DH>(out0b, wpack, stage, wxbuf,
                          p0, pwx, tid - 256);
    }
}

// ============================================================================
extern "C" void kernel_launch(void* const* d_in, const int* in_sizes, int n_in,
                              void* d_out, int out_size)
{
    const float* x      = (const float*)d_in[0];
    const float* w0     = (const float*)d_in[1];
    const float* u0     = (const float*)d_in[2];
    const float* bg0    = (const float*)d_in[3];
    const float* bu0    = (const float*)d_in[4];
    const float* zeta0  = (const float*)d_in[5];
    const float* nu0    = (const float*)d_in[6];
    const float* lambd0 = (const float*)d_in[7];
    const float* gamma0 = (const float*)d_in[8];
    const float* w1     = (const float*)d_in[9];
    const float* u1     = (const float*)d_in[10];
    const float* bg1    = (const float*)d_in[11];
    const float* bu1    = (const float*)d_in[12];
    const float* zeta1  = (const float*)d_in[13];
    const float* nu1    = (const float*)d_in[14];
    const float* lambd1 = (const float*)d_in[15];
    const float* gamma1 = (const float*)d_in[16];
    (void)in_sizes; (void)n_in; (void)out_size;

    float* out = (float*)d_out;                    // out1: [B, S, H]
    float* hT0 = out + (size_t)DB * DS * DH;       // h_n[0]
    float* hT1 = hT0 + (size_t)DB * DH;            // h_n[1]

    static int smem_set = 0;
    const int smem_bytes = 65536 + 4096 + 1024;
    if (!smem_set) {
        cudaFuncSetAttribute(fused_kernel,
                             cudaFuncAttributeMaxDynamicSharedMemorySize, smem_bytes);
        smem_set = 1;
    }

    reset_kernel<<<1, 2048>>>();
    fused_kernel<<<2 * DB, 512, smem_bytes>>>(
        x, w0, u0, bg0, bu0, zeta0, nu0, lambd0, gamma0,
        w1, u1, bg1, bu1, zeta1, nu1, lambd1, gamma1,
        out, hT0, hT1);
}